// round 14
// baseline (speedup 1.0000x reference)
#include <cuda_runtime.h>
#include <math.h>

#define H 1024
#define W 1024
#define HW (H*W)
#define TX 56
#define TY 32
#define GR 40     // gray/hblur rows (TY + 8)
#define BW 60     // hblur/blurred width (TX + 4)
#define BR 36     // blurred rows (TY + 4)
#define MW 58     // msq width (TX + 2)
#define MH 34     // msq rows (TY + 2)
#define NT 512
#define NBX 19    // ceil(1024/56)

typedef unsigned long long u64;

__device__ int g_count = 0;
__device__ int g_ticket = 0;

__device__ __forceinline__ u64 pk(float lo, float hi) {
    u64 r; asm("mov.b64 %0,{%1,%2};" : "=l"(r) : "f"(lo), "f"(hi)); return r;
}
__device__ __forceinline__ void upk(u64 v, float& lo, float& hi) {
    asm("mov.b64 {%0,%1},%2;" : "=f"(lo), "=f"(hi) : "l"(v));
}
__device__ __forceinline__ u64 fadd2(u64 a, u64 b) {
    u64 r; asm("add.rn.f32x2 %0,%1,%2;" : "=l"(r) : "l"(a), "l"(b)); return r;
}
__device__ __forceinline__ u64 fmul2(u64 a, u64 b) {
    u64 r; asm("mul.rn.f32x2 %0,%1,%2;" : "=l"(r) : "l"(a), "l"(b)); return r;
}
__device__ __forceinline__ u64 ffma2(u64 a, u64 b, u64 c) {
    u64 r; asm("fma.rn.f32x2 %0,%1,%2,%3;" : "=l"(r) : "l"(a), "l"(b), "l"(c)); return r;
}
__device__ __forceinline__ u64 fneg2(u64 a) { return a ^ 0x8000000080000000ULL; }
__device__ __forceinline__ u64 fsub2(u64 a, u64 b) { return fadd2(a, fneg2(b)); }

__device__ __forceinline__ int reflecti(int c, int n) {
    if (c < 0) c = -c;
    if (c >= n) c = 2*n - 2 - c;
    return c;
}

#define GW0 0.05448868454964294f
#define GW1 0.24420134723186663f
#define GW2 0.4026199364369709f
#define T_LO 0.41421356237309503f
#define T_HI 2.414213562373095f
#define TH2  0.009999f

__device__ __forceinline__ int axis_off(float gx, float gy) {
    float ax = fabsf(gx), ay = fabsf(gy);
    if (ay <= T_LO * ax) return 1;
    if (ay >= T_HI * ax) return MW;
    return ((__float_as_int(gx) ^ __float_as_int(gy)) >= 0) ? (MW - 1) : (MW + 1);
}

__device__ __forceinline__ u64 tap5(u64 t0, u64 t1, u64 t2, u64 t3, u64 t4,
                                    u64 K0, u64 K1, u64 K2) {
    u64 acc = fmul2(fadd2(t0, t4), K0);
    acc = ffma2(fadd2(t1, t3), K1, acc);
    return ffma2(t2, K2, acc);
}

__global__ __launch_bounds__(NT, 4)
void edge_loss_kernel(const float* __restrict__ op, const float* __restrict__ gt,
                      float* __restrict__ out, float inv_n)
{
    __shared__ u64   bufA[GR * BW];   // hblur -> later msq [MH][MW]
    __shared__ u64   bufB[BR * BW];   // blurred
    __shared__ short snoff[TY * TX];
    __shared__ int   wsum[NT / 32];

    const int tid  = threadIdx.x;
    const int lane = tid & 31;
    const int wid  = tid >> 5;
    const int x0 = blockIdx.x * TX;
    const int y0 = blockIdx.y * TY;
    const size_t ib = (size_t)blockIdx.z * 3 * HW;
    const float* __restrict__ opi = op + ib;
    const float* __restrict__ gti = gt + ib;

    const u64 K0 = pk(GW0, GW0), K1 = pk(GW1, GW1), K2 = pk(GW2, GW2);
    const u64 TWO = pk(2.0f, 2.0f);

    const bool xedge = (blockIdx.x == 0) || (blockIdx.x == NBX - 1);
    const int  c0  = x0 - 4 + 2 * lane;
    const int  rc0 = reflecti(c0, W), rc1 = reflecti(c0 + 1, W);

    // ---- Stage 1+2 fused: gray (reflect) + hblur via shfl -> bufA[GR][BW] ----
    #pragma unroll 1
    for (int r = wid; r < GR; r += NT / 32) {
        int yy = reflecti(y0 - 4 + r, H);
        const float* ro = opi + yy * W;
        const float* rg = gti + yy * W;
        float ao0, ao1, ag0, ag1;
        if (!xedge) {
            float2 r_o = *(const float2*)(ro + c0);
            float2 g_o = *(const float2*)(ro + HW + c0);
            float2 b_o = *(const float2*)(ro + 2*HW + c0);
            float2 r_g = *(const float2*)(rg + c0);
            float2 g_g = *(const float2*)(rg + HW + c0);
            float2 b_g = *(const float2*)(rg + 2*HW + c0);
            ao0 = fmaf(0.299f, r_o.x, fmaf(0.587f, g_o.x, 0.114f*b_o.x));
            ao1 = fmaf(0.299f, r_o.y, fmaf(0.587f, g_o.y, 0.114f*b_o.y));
            ag0 = fmaf(0.299f, r_g.x, fmaf(0.587f, g_g.x, 0.114f*b_g.x));
            ag1 = fmaf(0.299f, r_g.y, fmaf(0.587f, g_g.y, 0.114f*b_g.y));
        } else {
            ao0 = fmaf(0.299f, ro[rc0], fmaf(0.587f, ro[HW+rc0], 0.114f*ro[2*HW+rc0]));
            ao1 = fmaf(0.299f, ro[rc1], fmaf(0.587f, ro[HW+rc1], 0.114f*ro[2*HW+rc1]));
            ag0 = fmaf(0.299f, rg[rc0], fmaf(0.587f, rg[HW+rc0], 0.114f*rg[2*HW+rc0]));
            ag1 = fmaf(0.299f, rg[rc1], fmaf(0.587f, rg[HW+rc1], 0.114f*rg[2*HW+rc1]));
        }
        u64 g0 = pk(ao0, ag0), g1 = pk(ao1, ag1);
        u64 gm0 = __shfl_up_sync(0xffffffffu, g0, 1);
        u64 gm1 = __shfl_up_sync(0xffffffffu, g1, 1);
        u64 gp0 = __shfl_down_sync(0xffffffffu, g0, 1);
        u64 gp1 = __shfl_down_sync(0xffffffffu, g1, 1);
        u64 h0 = tap5(gm0, gm1, g0, g1, gp0, K0, K1, K2);
        u64 h1 = tap5(gm1, g0, g1, gp0, gp1, K0, K1, K2);
        if (lane >= 1 && lane <= 30)
            *(ulonglong2*)&bufA[r * BW + 2*lane - 2] = make_ulonglong2(h0, h1);
    }
    __syncthreads();

    // ---- Stage 3: vblur 2-tall x 1-wide -> bufB[BR][BW] ----
    #pragma unroll 1
    for (int s = tid; s < (BR/2) * BW; s += NT) {
        int rg = s / BW;
        int j = s - rg * BW;
        int r0 = rg << 1;
        const u64* col = &bufA[r0 * BW + j];
        u64 t0 = col[0],      t1 = col[BW],   t2 = col[2*BW];
        u64 t3 = col[3*BW],   t4 = col[4*BW], t5 = col[5*BW];
        bufB[(r0 + 0) * BW + j] = tap5(t0, t1, t2, t3, t4, K0, K1, K2);
        bufB[(r0 + 1) * BW + j] = tap5(t1, t2, t3, t4, t5, K0, K1, K2);
    }
    __syncthreads();

    // ---- Patches: x edge-clamp then y edge-clamp of blurred field ----
    if (blockIdx.x == 0) {
        #pragma unroll 1
        for (int r = tid; r < BR; r += NT) {
            u64 v = bufB[r * BW + 2];
            bufB[r * BW + 0] = v;
            bufB[r * BW + 1] = v;
        }
        __syncthreads();
    } else if (blockIdx.x == NBX - 1) {
        int blast = (W - 1) - (x0 - 2);
        #pragma unroll 1
        for (int r = tid; r < BR; r += NT) {
            u64 v = bufB[r * BW + blast];
            bufB[r * BW + blast + 1] = v;
            bufB[r * BW + blast + 2] = v;
        }
        __syncthreads();
    }
    if (y0 == 0) {
        #pragma unroll 1
        for (int j = tid; j < BW; j += NT) {
            u64 v = bufB[2 * BW + j];
            bufB[0 * BW + j] = v;
            bufB[1 * BW + j] = v;
        }
        __syncthreads();
    } else if (y0 == H - TY) {
        #pragma unroll 1
        for (int j = tid; j < BW; j += NT) {
            u64 v = bufB[33 * BW + j];
            bufB[34 * BW + j] = v;
            bufB[35 * BW + j] = v;
        }
        __syncthreads();
    }

    // ---- Stage 4: warp-row Sobel with shfl neighbor exchange ----
    // Lane L owns blurred cols 2L,2L+1 of rows i..i+2; outputs msq cols
    // m0=2L-1 (needs left col via shfl_up) and m1=2L (needs right via shfl_down).
    // msq col m needs blurred cols m..m+2 ; msq (i,m) <-> px (i, m+3).
    #pragma unroll 1
    for (int i = wid; i < MH; i += NT / 32) {
        int le = min(lane, 29);
        const u64* base = &bufB[i * BW + 2 * le];
        ulonglong2 a0 = *(const ulonglong2*)(base);
        ulonglong2 a1 = *(const ulonglong2*)(base + BW);
        ulonglong2 a2 = *(const ulonglong2*)(base + 2 * BW);
        u64 l0 = __shfl_up_sync(0xffffffffu, a0.y, 1);
        u64 l1 = __shfl_up_sync(0xffffffffu, a1.y, 1);
        u64 l2 = __shfl_up_sync(0xffffffffu, a2.y, 1);
        u64 r0 = __shfl_down_sync(0xffffffffu, a0.x, 1);
        u64 r1 = __shfl_down_sync(0xffffffffu, a1.x, 1);
        u64 r2 = __shfl_down_sync(0xffffffffu, a2.x, 1);

        int y = y0 - 1 + i;
        #pragma unroll
        for (int dj = 0; dj < 2; dj++) {
            int m = 2 * lane - 1 + dj;
            if (lane <= 29 && m >= 0 && m < MW) {
                u64 c00 = dj ? a0.x : l0;
                u64 c01 = dj ? a0.y : a0.x;
                u64 c02 = dj ? r0   : a0.y;
                u64 c10 = dj ? a1.x : l1;
                u64 c12 = dj ? r1   : a1.y;
                u64 c20 = dj ? a2.x : l2;
                u64 c21 = dj ? a2.y : a2.x;
                u64 c22 = dj ? r2   : a2.y;
                u64 c11l = dj ? a1.y : a1.x;  (void)c11l;
                u64 gx = ffma2(fsub2(c12, c10), TWO, fadd2(fsub2(c02, c00), fsub2(c22, c20)));
                u64 gy = ffma2(fsub2(c21, c01), TWO, fadd2(fsub2(c20, c00), fsub2(c22, c02)));
                int x = x0 - 1 + m;
                u64 msq = ffma2(gx, gx, fmul2(gy, gy));
                if (!((unsigned)y < H && (unsigned)x < W)) msq = 0ULL;
                bufA[i * MW + m] = msq;
                if (i >= 1 && i <= TY && m >= 1 && m <= TX) {
                    float gxo, gxg, gyo, gyg;
                    upk(gx, gxo, gxg); upk(gy, gyo, gyg);
                    int oo = axis_off(gxo, gyo);
                    int og = axis_off(gxg, gyg);
                    snoff[(i - 1) * TX + (m - 1)] = (short)(oo | (og << 8));
                }
            }
        }
    }
    __syncthreads();

    // ---- Stage 5: NMS + threshold + XOR count ----
    int cnt = 0;
    const float* Bf = (const float*)bufA;
    #pragma unroll
    for (int k = 0; k < 4; k++) {
        int px = tid + k * NT;
        if (px < TY * TX) {
            int i = px / TX, j = px - i * TX;
            int ci = (i + 1) * MW + (j + 1);
            float co, cg;
            upk(bufA[ci], co, cg);
            int sv = snoff[px];
            int oo = sv & 0xff;
            int og = (sv >> 8) & 0xff;
            bool eo = (co > Bf[2*(ci + oo)])     & (co > Bf[2*(ci - oo)])     & (co > TH2);
            bool eg = (cg > Bf[2*(ci + og) + 1]) & (cg > Bf[2*(ci - og) + 1]) & (cg > TH2);
            cnt += (int)(eo != eg);
        }
    }

    // ---- block reduce + fused finalize ----
    #pragma unroll
    for (int o = 16; o > 0; o >>= 1)
        cnt += __shfl_down_sync(0xffffffffu, cnt, o);
    if ((tid & 31) == 0) wsum[tid >> 5] = cnt;
    __syncthreads();
    if (tid < (NT / 32)) {
        cnt = wsum[tid];
        #pragma unroll
        for (int o = (NT / 64); o > 0; o >>= 1)
            cnt += __shfl_down_sync(0xffffu, cnt, o);
        if (tid == 0) {
            atomicAdd(&g_count, cnt);
            __threadfence();
            int nb = gridDim.x * gridDim.y * gridDim.z;
            int t = atomicAdd(&g_ticket, 1);
            if (t == nb - 1) {
                out[0] = (float)atomicAdd(&g_count, 0) * inv_n;
                g_count = 0;
                g_ticket = 0;
            }
        }
    }
}

extern "C" void kernel_launch(void* const* d_in, const int* in_sizes, int n_in,
                              void* d_out, int out_size)
{
    const float* op = (const float*)d_in[0];
    const float* gt = (const float*)d_in[1];
    float* out = (float*)d_out;

    int batch = in_sizes[0] / (3 * HW);
    float inv_n = 1.0f / ((float)batch * HW);

    dim3 grid(NBX, H / TY, batch);
    edge_loss_kernel<<<grid, NT>>>(op, gt, out, inv_n);
}

// round 15
// speedup vs baseline: 1.1218x; 1.1218x over previous
#include <cuda_runtime.h>
#include <math.h>

#define H 1024
#define W 1024
#define HW (H*W)
#define TX 56
#define TY 32
#define GR 40     // gray/hblur rows (TY + 8)
#define BW 60     // hblur/blurred width (TX + 4)
#define BR 36     // blurred rows (TY + 4)
#define MW 58     // msq width (TX + 2)
#define MH 34     // msq rows (TY + 2)
#define NT 512
#define NBX 19    // ceil(1024/56)

typedef unsigned long long u64;

__device__ int g_count = 0;
__device__ int g_ticket = 0;

__device__ __forceinline__ u64 pk(float lo, float hi) {
    u64 r; asm("mov.b64 %0,{%1,%2};" : "=l"(r) : "f"(lo), "f"(hi)); return r;
}
__device__ __forceinline__ void upk(u64 v, float& lo, float& hi) {
    asm("mov.b64 {%0,%1},%2;" : "=f"(lo), "=f"(hi) : "l"(v));
}
__device__ __forceinline__ u64 fadd2(u64 a, u64 b) {
    u64 r; asm("add.rn.f32x2 %0,%1,%2;" : "=l"(r) : "l"(a), "l"(b)); return r;
}
__device__ __forceinline__ u64 fmul2(u64 a, u64 b) {
    u64 r; asm("mul.rn.f32x2 %0,%1,%2;" : "=l"(r) : "l"(a), "l"(b)); return r;
}
__device__ __forceinline__ u64 ffma2(u64 a, u64 b, u64 c) {
    u64 r; asm("fma.rn.f32x2 %0,%1,%2,%3;" : "=l"(r) : "l"(a), "l"(b), "l"(c)); return r;
}
__device__ __forceinline__ u64 fneg2(u64 a) { return a ^ 0x8000000080000000ULL; }
__device__ __forceinline__ u64 fsub2(u64 a, u64 b) { return fadd2(a, fneg2(b)); }

__device__ __forceinline__ int reflecti(int c, int n) {
    if (c < 0) c = -c;
    if (c >= n) c = 2*n - 2 - c;
    return c;
}

#define GW0 0.05448868454964294f
#define GW1 0.24420134723186663f
#define GW2 0.4026199364369709f
#define T_LO 0.41421356237309503f
#define T_HI 2.414213562373095f
#define TH2  0.009999f

__device__ __forceinline__ int axis_off(float gx, float gy) {
    float ax = fabsf(gx), ay = fabsf(gy);
    if (ay <= T_LO * ax) return 1;
    if (ay >= T_HI * ax) return MW;
    return ((__float_as_int(gx) ^ __float_as_int(gy)) >= 0) ? (MW - 1) : (MW + 1);
}

__device__ __forceinline__ u64 tap5(u64 t0, u64 t1, u64 t2, u64 t3, u64 t4,
                                    u64 K0, u64 K1, u64 K2) {
    u64 acc = fmul2(fadd2(t0, t4), K0);
    acc = ffma2(fadd2(t1, t3), K1, acc);
    return ffma2(t2, K2, acc);
}

__global__ __launch_bounds__(NT, 4)
void edge_loss_kernel(const float* __restrict__ op, const float* __restrict__ gt,
                      float* __restrict__ out, float inv_n)
{
    __shared__ u64   bufA[GR * BW];   // hblur -> later msq [MH][MW]
    __shared__ u64   bufB[BR * BW];   // blurred
    __shared__ short snoff[TY * TX];
    __shared__ int   wsum[NT / 32];

    const int tid  = threadIdx.x;
    const int lane = tid & 31;
    const int wid  = tid >> 5;
    const int x0 = blockIdx.x * TX;
    const int y0 = blockIdx.y * TY;
    const size_t ib = (size_t)blockIdx.z * 3 * HW;
    const float* __restrict__ opi = op + ib;
    const float* __restrict__ gti = gt + ib;

    const u64 K0 = pk(GW0, GW0), K1 = pk(GW1, GW1), K2 = pk(GW2, GW2);
    const u64 TWO = pk(2.0f, 2.0f);

    const bool xedge = (blockIdx.x == 0) || (blockIdx.x == NBX - 1);
    const int  half = lane >> 4;        // which of the 2 rows this warp-iter covers
    const int  li   = lane & 15;        // lane within 16-wide row group
    const int  gcol = x0 - 4 + 4 * li;  // first gray col owned (4 px/lane)

    // ---- Stage 1+2 fused: gray (reflect) + hblur, 4px/lane, 2 rows/warp ----
    #pragma unroll 1
    for (int pr = wid; pr < GR / 2; pr += NT / 32) {
        int r = 2 * pr + half;
        int yy = reflecti(y0 - 4 + r, H);
        const float* ro = opi + yy * W;
        const float* rg = gti + yy * W;
        u64 g0, g1, g2, g3;
        if (!xedge) {
            float4 r_o = *(const float4*)(ro + gcol);
            float4 g_o = *(const float4*)(ro + HW + gcol);
            float4 b_o = *(const float4*)(ro + 2*HW + gcol);
            float4 r_g = *(const float4*)(rg + gcol);
            float4 g_g = *(const float4*)(rg + HW + gcol);
            float4 b_g = *(const float4*)(rg + 2*HW + gcol);
            g0 = pk(fmaf(0.299f, r_o.x, fmaf(0.587f, g_o.x, 0.114f*b_o.x)),
                    fmaf(0.299f, r_g.x, fmaf(0.587f, g_g.x, 0.114f*b_g.x)));
            g1 = pk(fmaf(0.299f, r_o.y, fmaf(0.587f, g_o.y, 0.114f*b_o.y)),
                    fmaf(0.299f, r_g.y, fmaf(0.587f, g_g.y, 0.114f*b_g.y)));
            g2 = pk(fmaf(0.299f, r_o.z, fmaf(0.587f, g_o.z, 0.114f*b_o.z)),
                    fmaf(0.299f, r_g.z, fmaf(0.587f, g_g.z, 0.114f*b_g.z)));
            g3 = pk(fmaf(0.299f, r_o.w, fmaf(0.587f, g_o.w, 0.114f*b_o.w)),
                    fmaf(0.299f, r_g.w, fmaf(0.587f, g_g.w, 0.114f*b_g.w)));
        } else {
            u64 gv[4];
            #pragma unroll
            for (int k = 0; k < 4; k++) {
                int rc = reflecti(gcol + k, W);
                gv[k] = pk(fmaf(0.299f, ro[rc], fmaf(0.587f, ro[HW+rc], 0.114f*ro[2*HW+rc])),
                           fmaf(0.299f, rg[rc], fmaf(0.587f, rg[HW+rc], 0.114f*rg[2*HW+rc])));
            }
            g0 = gv[0]; g1 = gv[1]; g2 = gv[2]; g3 = gv[3];
        }
        u64 l2 = __shfl_up_sync(0xffffffffu, g2, 1, 16);
        u64 l3 = __shfl_up_sync(0xffffffffu, g3, 1, 16);
        u64 r0v = __shfl_down_sync(0xffffffffu, g0, 1, 16);
        u64 r1v = __shfl_down_sync(0xffffffffu, g1, 1, 16);
        u64 h0 = tap5(l2, l3, g0, g1, g2, K0, K1, K2);
        u64 h1 = tap5(l3, g0, g1, g2, g3, K0, K1, K2);
        if (li >= 1)
            *(ulonglong2*)&bufA[r * BW + 4*li - 2] = make_ulonglong2(h0, h1);
        u64 h2 = tap5(g0, g1, g2, g3, r0v, K0, K1, K2);
        u64 h3 = tap5(g1, g2, g3, r0v, r1v, K0, K1, K2);
        if (li <= 14)
            *(ulonglong2*)&bufA[r * BW + 4*li] = make_ulonglong2(h2, h3);
    }
    __syncthreads();

    // ---- Stage 3: vblur 3-tall x 1-wide -> bufB[BR][BW] ----
    #pragma unroll 1
    for (int s = tid; s < (BR/3) * BW; s += NT) {
        int rg = s / BW;
        int j = s - rg * BW;
        int r0 = rg * 3;
        const u64* col = &bufA[r0 * BW + j];
        u64 t0 = col[0],    t1 = col[BW],   t2 = col[2*BW], t3 = col[3*BW];
        u64 t4 = col[4*BW], t5 = col[5*BW], t6 = col[6*BW];
        bufB[(r0 + 0) * BW + j] = tap5(t0, t1, t2, t3, t4, K0, K1, K2);
        bufB[(r0 + 1) * BW + j] = tap5(t1, t2, t3, t4, t5, K0, K1, K2);
        bufB[(r0 + 2) * BW + j] = tap5(t2, t3, t4, t5, t6, K0, K1, K2);
    }
    __syncthreads();

    // ---- Patches: x edge-clamp then y edge-clamp of blurred field ----
    if (blockIdx.x == 0) {
        #pragma unroll 1
        for (int r = tid; r < BR; r += NT) {
            u64 v = bufB[r * BW + 2];
            bufB[r * BW + 0] = v;
            bufB[r * BW + 1] = v;
        }
        __syncthreads();
    } else if (blockIdx.x == NBX - 1) {
        int blast = (W - 1) - (x0 - 2);
        #pragma unroll 1
        for (int r = tid; r < BR; r += NT) {
            u64 v = bufB[r * BW + blast];
            bufB[r * BW + blast + 1] = v;
            bufB[r * BW + blast + 2] = v;
        }
        __syncthreads();
    }
    if (y0 == 0) {
        #pragma unroll 1
        for (int j = tid; j < BW; j += NT) {
            u64 v = bufB[2 * BW + j];
            bufB[0 * BW + j] = v;
            bufB[1 * BW + j] = v;
        }
        __syncthreads();
    } else if (y0 == H - TY) {
        #pragma unroll 1
        for (int j = tid; j < BW; j += NT) {
            u64 v = bufB[33 * BW + j];
            bufB[34 * BW + j] = v;
            bufB[35 * BW + j] = v;
        }
        __syncthreads();
    }

    // ---- Stage 4: Sobel/msq 1x2 -> bufA[MH][MW] + packed NMS offsets (R12) ----
    #pragma unroll 1
    for (int s = tid; s < MH * 29; s += NT) {
        int i = s / 29;
        int cp = s - i * 29;
        int p = 3 + 2 * cp;
        const ulonglong2* r0p = (const ulonglong2*)&bufB[(i + 0) * BW + (p - 3)];
        const ulonglong2* r1p = (const ulonglong2*)&bufB[(i + 1) * BW + (p - 3)];
        const ulonglong2* r2p = (const ulonglong2*)&bufB[(i + 2) * BW + (p - 3)];
        ulonglong2 r0a = r0p[0], r0b = r0p[1];
        ulonglong2 r1a = r1p[0], r1b = r1p[1];
        ulonglong2 r2a = r2p[0], r2b = r2p[1];

        int y = y0 - 1 + i;
        u64 mres[2];
        #pragma unroll
        for (int dj = 0; dj < 2; dj++) {
            u64 a00 = dj ? r0a.y : r0a.x;
            u64 a01 = dj ? r0b.x : r0a.y;
            u64 a02 = dj ? r0b.y : r0b.x;
            u64 a10 = dj ? r1a.y : r1a.x;
            u64 a12 = dj ? r1b.y : r1b.x;
            u64 a20 = dj ? r2a.y : r2a.x;
            u64 a21 = dj ? r2b.x : r2a.y;
            u64 a22 = dj ? r2b.y : r2b.x;
            u64 gx = ffma2(fsub2(a12, a10), TWO, fadd2(fsub2(a02, a00), fsub2(a22, a20)));
            u64 gy = ffma2(fsub2(a21, a01), TWO, fadd2(fsub2(a20, a00), fsub2(a22, a02)));
            int px = p + dj;
            int x = x0 - 4 + px;
            u64 msq = ffma2(gx, gx, fmul2(gy, gy));
            if (!((unsigned)y < H && (unsigned)x < W)) msq = 0ULL;
            mres[dj] = msq;
            if (i >= 1 && i <= TY && px >= 4 && px <= 59) {
                float gxo, gxg, gyo, gyg;
                upk(gx, gxo, gxg); upk(gy, gyo, gyg);
                int oo = axis_off(gxo, gyo);
                int og = axis_off(gxg, gyg);
                snoff[(i - 1) * TX + (px - 4)] = (short)(oo | (og << 8));
            }
        }
        *(ulonglong2*)&bufA[i * MW + (p - 3)] = make_ulonglong2(mres[0], mres[1]);
    }
    __syncthreads();

    // ---- Stage 5: NMS + threshold + XOR count ----
    int cnt = 0;
    const float* Bf = (const float*)bufA;
    #pragma unroll
    for (int k = 0; k < 4; k++) {
        int px = tid + k * NT;
        if (px < TY * TX) {
            int i = px / TX, j = px - i * TX;
            int ci = (i + 1) * MW + (j + 1);
            float co, cg;
            upk(bufA[ci], co, cg);
            int sv = snoff[px];
            int oo = sv & 0xff;
            int og = (sv >> 8) & 0xff;
            bool eo = (co > Bf[2*(ci + oo)])     & (co > Bf[2*(ci - oo)])     & (co > TH2);
            bool eg = (cg > Bf[2*(ci + og) + 1]) & (cg > Bf[2*(ci - og) + 1]) & (cg > TH2);
            cnt += (int)(eo != eg);
        }
    }

    // ---- block reduce + fused finalize ----
    #pragma unroll
    for (int o = 16; o > 0; o >>= 1)
        cnt += __shfl_down_sync(0xffffffffu, cnt, o);
    if ((tid & 31) == 0) wsum[tid >> 5] = cnt;
    __syncthreads();
    if (tid < (NT / 32)) {
        cnt = wsum[tid];
        #pragma unroll
        for (int o = (NT / 64); o > 0; o >>= 1)
            cnt += __shfl_down_sync(0xffffu, cnt, o);
        if (tid == 0) {
            atomicAdd(&g_count, cnt);
            __threadfence();
            int nb = gridDim.x * gridDim.y * gridDim.z;
            int t = atomicAdd(&g_ticket, 1);
            if (t == nb - 1) {
                out[0] = (float)atomicAdd(&g_count, 0) * inv_n;
                g_count = 0;
                g_ticket = 0;
            }
        }
    }
}

extern "C" void kernel_launch(void* const* d_in, const int* in_sizes, int n_in,
                              void* d_out, int out_size)
{
    const float* op = (const float*)d_in[0];
    const float* gt = (const float*)d_in[1];
    float* out = (float*)d_out;

    int batch = in_sizes[0] / (3 * HW);
    float inv_n = 1.0f / ((float)batch * HW);

    dim3 grid(NBX, H / TY, batch);
    edge_loss_kernel<<<grid, NT>>>(op, gt, out, inv_n);
}

// round 16
// speedup vs baseline: 1.1905x; 1.0613x over previous
#include <cuda_runtime.h>
#include <math.h>

#define H 1024
#define W 1024
#define HW (H*W)
#define TX 56
#define TY 32
#define GR 40     // gray/hblur rows (TY + 8)
#define BW 60     // hblur/blurred width (TX + 4)
#define BR 36     // blurred rows (TY + 4)
#define MW 58     // msq width (TX + 2)
#define MH 34     // msq rows (TY + 2)
#define NT 512
#define NBX 19    // ceil(1024/56)
#define MPLANE (MH*MW)   // 1972 floats per msq plane

typedef unsigned long long u64;

__device__ int g_count = 0;
__device__ int g_ticket = 0;

__device__ __forceinline__ u64 pk(float lo, float hi) {
    u64 r; asm("mov.b64 %0,{%1,%2};" : "=l"(r) : "f"(lo), "f"(hi)); return r;
}
__device__ __forceinline__ void upk(u64 v, float& lo, float& hi) {
    asm("mov.b64 {%0,%1},%2;" : "=f"(lo), "=f"(hi) : "l"(v));
}
__device__ __forceinline__ u64 fadd2(u64 a, u64 b) {
    u64 r; asm("add.rn.f32x2 %0,%1,%2;" : "=l"(r) : "l"(a), "l"(b)); return r;
}
__device__ __forceinline__ u64 fmul2(u64 a, u64 b) {
    u64 r; asm("mul.rn.f32x2 %0,%1,%2;" : "=l"(r) : "l"(a), "l"(b)); return r;
}
__device__ __forceinline__ u64 ffma2(u64 a, u64 b, u64 c) {
    u64 r; asm("fma.rn.f32x2 %0,%1,%2,%3;" : "=l"(r) : "l"(a), "l"(b), "l"(c)); return r;
}
__device__ __forceinline__ u64 fneg2(u64 a) { return a ^ 0x8000000080000000ULL; }
__device__ __forceinline__ u64 fsub2(u64 a, u64 b) { return fadd2(a, fneg2(b)); }

__device__ __forceinline__ int reflecti(int c, int n) {
    if (c < 0) c = -c;
    if (c >= n) c = 2*n - 2 - c;
    return c;
}

#define GW0 0.05448868454964294f
#define GW1 0.24420134723186663f
#define GW2 0.4026199364369709f
#define T_LO 0.41421356237309503f
#define T_HI 2.414213562373095f
#define TH2  0.009999f

__device__ __forceinline__ int axis_off(float gx, float gy) {
    float ax = fabsf(gx), ay = fabsf(gy);
    if (ay <= T_LO * ax) return 1;
    if (ay >= T_HI * ax) return MW;
    return ((__float_as_int(gx) ^ __float_as_int(gy)) >= 0) ? (MW - 1) : (MW + 1);
}

__device__ __forceinline__ u64 tap5(u64 t0, u64 t1, u64 t2, u64 t3, u64 t4,
                                    u64 K0, u64 K1, u64 K2) {
    u64 acc = fmul2(fadd2(t0, t4), K0);
    acc = ffma2(fadd2(t1, t3), K1, acc);
    return ffma2(t2, K2, acc);
}

__global__ __launch_bounds__(NT, 4)
void edge_loss_kernel(const float* __restrict__ op, const float* __restrict__ gt,
                      float* __restrict__ out, float inv_n)
{
    __shared__ u64   bufA[GR * BW];   // hblur -> later 2 planar msq fields
    __shared__ u64   bufB[BR * BW];   // blurred
    __shared__ short snoff[TY * TX];
    __shared__ int   wsum[NT / 32];

    float* msqO = (float*)bufA;            // [MH*MW] op-plane
    float* msqG = msqO + MPLANE;           // [MH*MW] gt-plane

    const int tid  = threadIdx.x;
    const int lane = tid & 31;
    const int wid  = tid >> 5;
    const int x0 = blockIdx.x * TX;
    const int y0 = blockIdx.y * TY;
    const size_t ib = (size_t)blockIdx.z * 3 * HW;
    const float* __restrict__ opi = op + ib;
    const float* __restrict__ gti = gt + ib;

    const u64 K0 = pk(GW0, GW0), K1 = pk(GW1, GW1), K2 = pk(GW2, GW2);
    const u64 TWO = pk(2.0f, 2.0f);

    const bool xedge = (blockIdx.x == 0) || (blockIdx.x == NBX - 1);
    const int  c0  = x0 - 4 + 2 * lane;
    const int  rc0 = reflecti(c0, W), rc1 = reflecti(c0 + 1, W);

    // ---- Stage 1+2 fused: gray (reflect) + hblur via shfl -> bufA[GR][BW] ----
    #pragma unroll 1
    for (int r = wid; r < GR; r += NT / 32) {
        int yy = reflecti(y0 - 4 + r, H);
        const float* ro = opi + yy * W;
        const float* rg = gti + yy * W;
        float ao0, ao1, ag0, ag1;
        if (!xedge) {
            float2 r_o = *(const float2*)(ro + c0);
            float2 g_o = *(const float2*)(ro + HW + c0);
            float2 b_o = *(const float2*)(ro + 2*HW + c0);
            float2 r_g = *(const float2*)(rg + c0);
            float2 g_g = *(const float2*)(rg + HW + c0);
            float2 b_g = *(const float2*)(rg + 2*HW + c0);
            ao0 = fmaf(0.299f, r_o.x, fmaf(0.587f, g_o.x, 0.114f*b_o.x));
            ao1 = fmaf(0.299f, r_o.y, fmaf(0.587f, g_o.y, 0.114f*b_o.y));
            ag0 = fmaf(0.299f, r_g.x, fmaf(0.587f, g_g.x, 0.114f*b_g.x));
            ag1 = fmaf(0.299f, r_g.y, fmaf(0.587f, g_g.y, 0.114f*b_g.y));
        } else {
            ao0 = fmaf(0.299f, ro[rc0], fmaf(0.587f, ro[HW+rc0], 0.114f*ro[2*HW+rc0]));
            ao1 = fmaf(0.299f, ro[rc1], fmaf(0.587f, ro[HW+rc1], 0.114f*ro[2*HW+rc1]));
            ag0 = fmaf(0.299f, rg[rc0], fmaf(0.587f, rg[HW+rc0], 0.114f*rg[2*HW+rc0]));
            ag1 = fmaf(0.299f, rg[rc1], fmaf(0.587f, rg[HW+rc1], 0.114f*rg[2*HW+rc1]));
        }
        u64 g0 = pk(ao0, ag0), g1 = pk(ao1, ag1);
        u64 gm0 = __shfl_up_sync(0xffffffffu, g0, 1);
        u64 gm1 = __shfl_up_sync(0xffffffffu, g1, 1);
        u64 gp0 = __shfl_down_sync(0xffffffffu, g0, 1);
        u64 gp1 = __shfl_down_sync(0xffffffffu, g1, 1);
        u64 h0 = tap5(gm0, gm1, g0, g1, gp0, K0, K1, K2);
        u64 h1 = tap5(gm1, g0, g1, gp0, gp1, K0, K1, K2);
        if (lane >= 1 && lane <= 30)
            *(ulonglong2*)&bufA[r * BW + 2*lane - 2] = make_ulonglong2(h0, h1);
    }
    __syncthreads();

    // ---- Stage 3: vblur 3-tall x 1-wide -> bufB[BR][BW] ----
    #pragma unroll 1
    for (int s = tid; s < (BR/3) * BW; s += NT) {
        int rg = s / BW;
        int j = s - rg * BW;
        int r0 = rg * 3;
        const u64* col = &bufA[r0 * BW + j];
        u64 t0 = col[0],    t1 = col[BW],   t2 = col[2*BW], t3 = col[3*BW];
        u64 t4 = col[4*BW], t5 = col[5*BW], t6 = col[6*BW];
        bufB[(r0 + 0) * BW + j] = tap5(t0, t1, t2, t3, t4, K0, K1, K2);
        bufB[(r0 + 1) * BW + j] = tap5(t1, t2, t3, t4, t5, K0, K1, K2);
        bufB[(r0 + 2) * BW + j] = tap5(t2, t3, t4, t5, t6, K0, K1, K2);
    }
    __syncthreads();

    // ---- Patches: x edge-clamp then y edge-clamp of blurred field ----
    if (blockIdx.x == 0) {
        #pragma unroll 1
        for (int r = tid; r < BR; r += NT) {
            u64 v = bufB[r * BW + 2];
            bufB[r * BW + 0] = v;
            bufB[r * BW + 1] = v;
        }
        __syncthreads();
    } else if (blockIdx.x == NBX - 1) {
        int blast = (W - 1) - (x0 - 2);
        #pragma unroll 1
        for (int r = tid; r < BR; r += NT) {
            u64 v = bufB[r * BW + blast];
            bufB[r * BW + blast + 1] = v;
            bufB[r * BW + blast + 2] = v;
        }
        __syncthreads();
    }
    if (y0 == 0) {
        #pragma unroll 1
        for (int j = tid; j < BW; j += NT) {
            u64 v = bufB[2 * BW + j];
            bufB[0 * BW + j] = v;
            bufB[1 * BW + j] = v;
        }
        __syncthreads();
    } else if (y0 == H - TY) {
        #pragma unroll 1
        for (int j = tid; j < BW; j += NT) {
            u64 v = bufB[33 * BW + j];
            bufB[34 * BW + j] = v;
            bufB[35 * BW + j] = v;
        }
        __syncthreads();
    }

    // ---- Stage 4: Sobel/msq 1x2 -> planar msqO/msqG + packed NMS offsets ----
    #pragma unroll 1
    for (int s = tid; s < MH * 29; s += NT) {
        int i = s / 29;
        int cp = s - i * 29;
        int p = 3 + 2 * cp;
        const ulonglong2* r0p = (const ulonglong2*)&bufB[(i + 0) * BW + (p - 3)];
        const ulonglong2* r1p = (const ulonglong2*)&bufB[(i + 1) * BW + (p - 3)];
        const ulonglong2* r2p = (const ulonglong2*)&bufB[(i + 2) * BW + (p - 3)];
        ulonglong2 r0a = r0p[0], r0b = r0p[1];
        ulonglong2 r1a = r1p[0], r1b = r1p[1];
        ulonglong2 r2a = r2p[0], r2b = r2p[1];

        int y = y0 - 1 + i;
        float mo[2], mg[2];
        #pragma unroll
        for (int dj = 0; dj < 2; dj++) {
            u64 a00 = dj ? r0a.y : r0a.x;
            u64 a01 = dj ? r0b.x : r0a.y;
            u64 a02 = dj ? r0b.y : r0b.x;
            u64 a10 = dj ? r1a.y : r1a.x;
            u64 a12 = dj ? r1b.y : r1b.x;
            u64 a20 = dj ? r2a.y : r2a.x;
            u64 a21 = dj ? r2b.x : r2a.y;
            u64 a22 = dj ? r2b.y : r2b.x;
            u64 gx = ffma2(fsub2(a12, a10), TWO, fadd2(fsub2(a02, a00), fsub2(a22, a20)));
            u64 gy = ffma2(fsub2(a21, a01), TWO, fadd2(fsub2(a20, a00), fsub2(a22, a02)));
            int px = p + dj;
            int x = x0 - 4 + px;
            u64 msq = ffma2(gx, gx, fmul2(gy, gy));
            if (!((unsigned)y < H && (unsigned)x < W)) msq = 0ULL;
            upk(msq, mo[dj], mg[dj]);
            if (i >= 1 && i <= TY && px >= 4 && px <= 59) {
                float gxo, gxg, gyo, gyg;
                upk(gx, gxo, gxg); upk(gy, gyo, gyg);
                int oo = axis_off(gxo, gyo);
                int og = axis_off(gxg, gyg);
                snoff[(i - 1) * TX + (px - 4)] = (short)(oo | (og << 8));
            }
        }
        int mi = i * MW + (p - 3);
        *(float2*)&msqO[mi] = make_float2(mo[0], mo[1]);
        *(float2*)&msqG[mi] = make_float2(mg[0], mg[1]);
    }
    __syncthreads();

    // ---- Stage 5: NMS + threshold + XOR count (planar, stride-4B loads) ----
    int cnt = 0;
    #pragma unroll
    for (int k = 0; k < 4; k++) {
        int px = tid + k * NT;
        if (px < TY * TX) {
            int i = px / TX, j = px - i * TX;
            int ci = (i + 1) * MW + (j + 1);
            float co = msqO[ci];
            float cg = msqG[ci];
            int sv = snoff[px];
            int oo = sv & 0xff;
            int og = (sv >> 8) & 0xff;
            bool eo = (co > msqO[ci + oo]) & (co > msqO[ci - oo]) & (co > TH2);
            bool eg = (cg > msqG[ci + og]) & (cg > msqG[ci - og]) & (cg > TH2);
            cnt += (int)(eo != eg);
        }
    }

    // ---- block reduce + fused finalize ----
    #pragma unroll
    for (int o = 16; o > 0; o >>= 1)
        cnt += __shfl_down_sync(0xffffffffu, cnt, o);
    if ((tid & 31) == 0) wsum[tid >> 5] = cnt;
    __syncthreads();
    if (tid < (NT / 32)) {
        cnt = wsum[tid];
        #pragma unroll
        for (int o = (NT / 64); o > 0; o >>= 1)
            cnt += __shfl_down_sync(0xffffu, cnt, o);
        if (tid == 0) {
            atomicAdd(&g_count, cnt);
            __threadfence();
            int nb = gridDim.x * gridDim.y * gridDim.z;
            int t = atomicAdd(&g_ticket, 1);
            if (t == nb - 1) {
                out[0] = (float)atomicAdd(&g_count, 0) * inv_n;
                g_count = 0;
                g_ticket = 0;
            }
        }
    }
}

extern "C" void kernel_launch(void* const* d_in, const int* in_sizes, int n_in,
                              void* d_out, int out_size)
{
    const float* op = (const float*)d_in[0];
    const float* gt = (const float*)d_in[1];
    float* out = (float*)d_out;

    int batch = in_sizes[0] / (3 * HW);
    float inv_n = 1.0f / ((float)batch * HW);

    dim3 grid(NBX, H / TY, batch);
    edge_loss_kernel<<<grid, NT>>>(op, gt, out, inv_n);
}